// round 2
// baseline (speedup 1.0000x reference)
#include <cuda_runtime.h>
#include <cuda_bf16.h>

typedef unsigned long long U64;

static __device__ __forceinline__ void fma2(U64 &d, U64 a, U64 b) {
    asm("fma.rn.f32x2 %0, %1, %2, %0;" : "+l"(d) : "l"(a), "l"(b));
}
static __device__ __forceinline__ U64 dupf(float v) {
    U64 r; asm("mov.b64 %0, {%1, %1};" : "=l"(r) : "f"(v)); return r;
}
static __device__ __forceinline__ void unpk(U64 v, float &lo, float &hi) {
    asm("mov.b64 {%0, %1}, %2;" : "=f"(lo), "=f"(hi) : "l"(v));
}

#define B_  8
#define C_  256
#define HW_ 4096
#define M_  512

// device-global scratch (no allocations allowed)
__device__ float g_IG[B_ * C_];
__device__ float g_gate[B_ * C_];
__device__ float g_P[M_ * C_];                 // P[m][o] = sum_c W2[o][c]*mem[m][c]
__device__ float g_x[(size_t)B_ * C_ * HW_];   // pre-depthwise activations

// ---------------- K1: per-(b,c) spatial mean ----------------
__global__ void k_mean(const float* __restrict__ img) {
    __shared__ float red[256];
    int bc = blockIdx.x;
    const float4* p = (const float4*)(img + (size_t)bc * HW_);
    float s = 0.f;
    for (int i = threadIdx.x; i < HW_ / 4; i += 256) {
        float4 v = p[i];
        s += (v.x + v.y) + (v.z + v.w);
    }
    red[threadIdx.x] = s;
    __syncthreads();
    for (int st = 128; st > 0; st >>= 1) {
        if (threadIdx.x < st) red[threadIdx.x] += red[threadIdx.x + st];
        __syncthreads();
    }
    if (threadIdx.x == 0) g_IG[bc] = red[0] * (1.f / (float)HW_);
}

// ---------------- K2: global path -> gate = sigmoid(softmax(IG.memT).mem + IG) ----------------
__global__ void k_global(const float* __restrict__ mem) {
    __shared__ float sc[M_];
    __shared__ float ig[C_];
    __shared__ float red[256];
    int b = blockIdx.x, t = threadIdx.x;
    ig[t] = g_IG[b * C_ + t];
    __syncthreads();
    #pragma unroll
    for (int r = 0; r < 2; r++) {
        int m = t + r * 256;
        const float* mr = mem + (size_t)m * C_;
        float a = 0.f;
        for (int c = 0; c < C_; c += 4) {
            float4 mv = *(const float4*)(mr + c);
            a += ig[c] * mv.x + ig[c + 1] * mv.y + ig[c + 2] * mv.z + ig[c + 3] * mv.w;
        }
        sc[m] = a;
    }
    __syncthreads();
    red[t] = fmaxf(sc[t], sc[t + 256]);
    __syncthreads();
    for (int st = 128; st > 0; st >>= 1) {
        if (t < st) red[t] = fmaxf(red[t], red[t + st]);
        __syncthreads();
    }
    float mx = red[0];
    __syncthreads();
    float e0 = expf(sc[t] - mx), e1 = expf(sc[t + 256] - mx);
    sc[t] = e0; sc[t + 256] = e1;
    red[t] = e0 + e1;
    __syncthreads();
    for (int st = 128; st > 0; st >>= 1) {
        if (t < st) red[t] += red[t + st];
        __syncthreads();
    }
    float inv = 1.f / red[0];
    float acc = 0.f;
    for (int m = 0; m < M_; m++) acc += sc[m] * mem[(size_t)m * C_ + t];
    float mr2 = acc * inv + ig[t];
    g_gate[b * C_ + t] = 1.f / (1.f + expf(-mr2));
}

// ---------------- K2p: P[m][o] = W2[o,:] . mem[m,:] ----------------
__global__ void k_pmat(const float* __restrict__ mem, const float* __restrict__ fw) {
    __shared__ float row[C_];
    int m = blockIdx.x, o = threadIdx.x;
    row[o] = mem[(size_t)m * C_ + o];
    __syncthreads();
    const float* wr = fw + (size_t)o * 512 + 256;
    float a = 0.f;
    for (int c = 0; c < C_; c += 4) {
        float4 w4 = *(const float4*)(wr + c);
        a += w4.x * row[c] + w4.y * row[c + 1] + w4.z * row[c + 2] + w4.w * row[c + 3];
    }
    g_P[m * C_ + o] = a;
}

// ---------------- K3: main fused kernel (scores + top2 + fusion 1x1) ----------------
#define TPX 128
#define XS_ST 132
#define MS_ST 36
#define SB_ST 132
#define OFF_XS 0
#define OFF_MS (OFF_XS + 256 * XS_ST)     /* 33792 */
#define OFF_SB (OFF_MS + 256 * MS_ST)     /* 43008 */
#define OFF_GS (OFF_SB + 32 * SB_ST)      /* 47232 */
#define OFF_BS (OFF_GS + 256)             /* 47488 */
#define OFF_A0 (OFF_BS + 256)             /* 47744 */
#define OFF_A1 (OFF_A0 + 128)             /* 47872 */
#define OFF_I0 (OFF_A1 + 128)             /* 48000 */
#define OFF_I1 (OFF_I0 + 128)             /* 48128 */
#define SMEM_FLOATS (OFF_I1 + 128)        /* 48256 */
#define SMEM_MAIN (SMEM_FLOATS * 4)       /* 193024 bytes */

static __device__ __forceinline__ void tile_fma(const float* __restrict__ Xs,
                                                const float* __restrict__ Ms,
                                                int px0, int mg0, U64* acc) {
    #pragma unroll 2
    for (int c = 0; c < 256; c++) {
        float4 f4 = *(const float4*)(Xs + c * XS_ST + px0);
        U64 fd0 = dupf(f4.x), fd1 = dupf(f4.y), fd2 = dupf(f4.z), fd3 = dupf(f4.w);
        const float* mrow = Ms + c * MS_ST + mg0;
        ulonglong2 ma = *(const ulonglong2*)(mrow);
        ulonglong2 mb = *(const ulonglong2*)(mrow + 4);
        fma2(acc[0],  fd0, ma.x); fma2(acc[1],  fd0, ma.y); fma2(acc[2],  fd0, mb.x); fma2(acc[3],  fd0, mb.y);
        fma2(acc[4],  fd1, ma.x); fma2(acc[5],  fd1, ma.y); fma2(acc[6],  fd1, mb.x); fma2(acc[7],  fd1, mb.y);
        fma2(acc[8],  fd2, ma.x); fma2(acc[9],  fd2, ma.y); fma2(acc[10], fd2, mb.x); fma2(acc[11], fd2, mb.y);
        fma2(acc[12], fd3, ma.x); fma2(acc[13], fd3, ma.y); fma2(acc[14], fd3, mb.x); fma2(acc[15], fd3, mb.y);
    }
}

__global__ void __launch_bounds__(128, 1) k_main(
    const float* __restrict__ img, const float* __restrict__ mem,
    const float* __restrict__ fw, const float* __restrict__ fb)
{
    extern __shared__ float sm[];
    float* Xs = sm + OFF_XS;   // [256 c][132] feature tile (pixel-minor)
    float* Ms = sm + OFF_MS;   // [256 c][36]  mem / W1 chunk, transposed
    float* Sb = sm + OFF_SB;   // [32 m][132]  score staging
    float* gS = sm + OFF_GS;
    float* bS = sm + OFF_BS;
    float* A0 = sm + OFF_A0;
    float* A1 = sm + OFF_A1;
    int*   I0 = (int*)(sm + OFF_I0);
    int*   I1 = (int*)(sm + OFF_I1);

    const int t   = threadIdx.x;
    const int b   = blockIdx.x >> 5;
    const int p0  = (blockIdx.x & 31) * TPX;
    const int px0 = 4 * (t & 31);
    const int mg0 = 8 * (t >> 5);

    gS[t] = g_gate[b * C_ + t];  gS[t + 128] = g_gate[b * C_ + t + 128];
    bS[t] = fb[t];               bS[t + 128] = fb[t + 128];

    const float* ib = img + (size_t)b * C_ * HW_ + p0;
    for (int c = 0; c < 256; c++) Xs[c * XS_ST + t] = ib[(size_t)c * HW_ + t];
    __syncthreads();

    float v0 = -3.402823466e38f, v1 = -3.402823466e38f;
    int bi0 = 0, bi1 = 0;

    // ========== scores X.memT + running top-2 ==========
    for (int mc = 0; mc < M_; mc += 32) {
        for (int i = t; i < 32 * 256; i += 128) {
            int r = i >> 8, c = i & 255;
            Ms[c * MS_ST + r] = mem[(size_t)(mc + r) * C_ + c];
        }
        __syncthreads();

        U64 acc[16];
        #pragma unroll
        for (int k = 0; k < 16; k++) acc[k] = 0ULL;
        tile_fma(Xs, Ms, px0, mg0, acc);

        #pragma unroll
        for (int i = 0; i < 4; i++)
            #pragma unroll
            for (int j = 0; j < 4; j++) {
                float lo, hi; unpk(acc[i * 4 + j], lo, hi);
                Sb[(mg0 + 2 * j) * SB_ST + px0 + i] = lo;
                Sb[(mg0 + 2 * j + 1) * SB_ST + px0 + i] = hi;
            }
        __syncthreads();

        // thread t owns pixel t: scan 32 scores, update top-2
        #pragma unroll 4
        for (int m = 0; m < 32; m++) {
            float s = Sb[m * SB_ST + t];
            int gm = mc + m;
            if (s > v0) { v1 = v0; bi1 = bi0; v0 = s; bi0 = gm; }
            else if (s > v1) { v1 = s; bi1 = gm; }
        }
        __syncthreads();
    }

    // attn softmax over (v0 >= v1)
    {
        float e1 = expf(v1 - v0);
        float a0 = 1.f / (1.f + e1);
        A0[t] = a0; A1[t] = e1 * a0; I0[t] = bi0; I1[t] = bi1;
        // scale Xs by gate (global_comp) — thread t owns pixel column t
        for (int c = 0; c < 256; c++) Xs[c * XS_ST + t] *= gS[c];
    }
    __syncthreads();

    // ========== fusion: x = leaky(W1.(gate*X) + a0*P[i0] + a1*P[i1] + b) ==========
    for (int oc = 0; oc < C_; oc += 32) {
        for (int i = t; i < 32 * 256; i += 128) {
            int r = i >> 8, c = i & 255;
            Ms[c * MS_ST + r] = fw[(size_t)(oc + r) * 512 + c];
        }
        __syncthreads();

        U64 acc[16];
        #pragma unroll
        for (int k = 0; k < 16; k++) acc[k] = 0ULL;
        tile_fma(Xs, Ms, px0, mg0, acc);

        #pragma unroll
        for (int i = 0; i < 4; i++) {
            int p = px0 + i;
            float a0 = A0[p], a1 = A1[p];
            const float* P0 = g_P + (size_t)I0[p] * C_ + oc + mg0;
            const float* P1 = g_P + (size_t)I1[p] * C_ + oc + mg0;
            float4 q0a = *(const float4*)P0,       q0b = *(const float4*)(P0 + 4);
            float4 q1a = *(const float4*)P1,       q1b = *(const float4*)(P1 + 4);
            float pv[8];
            pv[0] = a0 * q0a.x + a1 * q1a.x;  pv[1] = a0 * q0a.y + a1 * q1a.y;
            pv[2] = a0 * q0a.z + a1 * q1a.z;  pv[3] = a0 * q0a.w + a1 * q1a.w;
            pv[4] = a0 * q0b.x + a1 * q1b.x;  pv[5] = a0 * q0b.y + a1 * q1b.y;
            pv[6] = a0 * q0b.z + a1 * q1b.z;  pv[7] = a0 * q0b.w + a1 * q1b.w;
            float* xout = g_x + ((size_t)b * C_ + oc + mg0) * HW_ + p0 + p;
            #pragma unroll
            for (int j = 0; j < 4; j++) {
                float lo, hi; unpk(acc[i * 4 + j], lo, hi);
                float vl = lo + pv[2 * j]     + bS[oc + mg0 + 2 * j];
                float vh = hi + pv[2 * j + 1] + bS[oc + mg0 + 2 * j + 1];
                vl = (vl > 0.f) ? vl : 0.2f * vl;
                vh = (vh > 0.f) ? vh : 0.2f * vh;
                xout[(size_t)(2 * j) * HW_] = vl;
                xout[(size_t)(2 * j + 1) * HW_] = vh;
            }
        }
        __syncthreads();
    }
}

// ---------------- K4: depthwise dilated 3x3 (d=2) + bias + leaky ----------------
__global__ void k_dw(const float* __restrict__ dw, const float* __restrict__ db,
                     float* __restrict__ out) {
    __shared__ float sx[4096];
    __shared__ float w[9];
    int bc = blockIdx.x;
    int c = bc & 255;
    int t = threadIdx.x;
    const float* xin = g_x + (size_t)bc * HW_;
    for (int i = t; i < 4096; i += 256) sx[i] = xin[i];
    if (t < 9) w[t] = dw[c * 9 + t];
    __syncthreads();
    float bias = db[c];
    for (int p = t; p < 4096; p += 256) {
        int y = p >> 6, x = p & 63;
        float s = bias;
        #pragma unroll
        for (int ky = 0; ky < 3; ky++) {
            int iy = y + 2 * ky - 2;
            if ((unsigned)iy < 64u) {
                #pragma unroll
                for (int kx = 0; kx < 3; kx++) {
                    int ix = x + 2 * kx - 2;
                    if ((unsigned)ix < 64u) s += w[ky * 3 + kx] * sx[(iy << 6) + ix];
                }
            }
        }
        out[(size_t)bc * HW_ + p] = (s > 0.f) ? s : 0.2f * s;
    }
}

extern "C" void kernel_launch(void* const* d_in, const int* in_sizes, int n_in,
                              void* d_out, int out_size) {
    const float* img = (const float*)d_in[0];
    const float* mem = (const float*)d_in[1];
    const float* fw  = (const float*)d_in[2];
    const float* fb  = (const float*)d_in[3];
    const float* dw  = (const float*)d_in[4];
    const float* db  = (const float*)d_in[5];
    float* out = (float*)d_out;

    cudaFuncSetAttribute(k_main, cudaFuncAttributeMaxDynamicSharedMemorySize, SMEM_MAIN);

    k_mean<<<B_ * C_, 256>>>(img);
    k_global<<<B_, 256>>>(mem);
    k_pmat<<<M_, 256>>>(mem, fw);
    k_main<<<B_ * (HW_ / TPX), 128, SMEM_MAIN>>>(img, mem, fw, fb);
    k_dw<<<B_ * C_, 256>>>(dw, db, out);
}

// round 3
// speedup vs baseline: 1.5268x; 1.5268x over previous
#include <cuda_runtime.h>
#include <cuda_bf16.h>

typedef unsigned long long U64;

static __device__ __forceinline__ void fma2(U64 &d, U64 a, U64 b) {
    asm("fma.rn.f32x2 %0, %1, %2, %0;" : "+l"(d) : "l"(a), "l"(b));
}
static __device__ __forceinline__ U64 dupf(float v) {
    U64 r; asm("mov.b64 %0, {%1, %1};" : "=l"(r) : "f"(v)); return r;
}
static __device__ __forceinline__ void unpk(U64 v, float &lo, float &hi) {
    asm("mov.b64 {%0, %1}, %2;" : "=f"(lo), "=f"(hi) : "l"(v));
}

#define B_  8
#define C_  256
#define HW_ 4096
#define M_  512

// device-global scratch (no allocations allowed)
__device__ float g_IG[B_ * C_];
__device__ float g_gate[B_ * C_];
__device__ float g_P[M_ * C_];                 // P[m][o] = sum_c W2[o][c]*mem[m][c]
__device__ float g_x[(size_t)B_ * C_ * HW_];   // pre-depthwise activations

// ---------------- K1: per-(b,c) spatial mean ----------------
__global__ void k_mean(const float* __restrict__ img) {
    __shared__ float red[256];
    int bc = blockIdx.x;
    const float4* p = (const float4*)(img + (size_t)bc * HW_);
    float s = 0.f;
    for (int i = threadIdx.x; i < HW_ / 4; i += 256) {
        float4 v = p[i];
        s += (v.x + v.y) + (v.z + v.w);
    }
    red[threadIdx.x] = s;
    __syncthreads();
    for (int st = 128; st > 0; st >>= 1) {
        if (threadIdx.x < st) red[threadIdx.x] += red[threadIdx.x + st];
        __syncthreads();
    }
    if (threadIdx.x == 0) g_IG[bc] = red[0] * (1.f / (float)HW_);
}

// ---------------- K2: global path -> gate ----------------
__global__ void k_global(const float* __restrict__ mem) {
    __shared__ float sc[M_];
    __shared__ float ig[C_];
    __shared__ float red[256];
    int b = blockIdx.x, t = threadIdx.x;
    ig[t] = g_IG[b * C_ + t];
    __syncthreads();
    #pragma unroll
    for (int r = 0; r < 2; r++) {
        int m = t + r * 256;
        const float* mr = mem + (size_t)m * C_;
        float a = 0.f;
        for (int c = 0; c < C_; c += 4) {
            float4 mv = *(const float4*)(mr + c);
            a += ig[c] * mv.x + ig[c + 1] * mv.y + ig[c + 2] * mv.z + ig[c + 3] * mv.w;
        }
        sc[m] = a;
    }
    __syncthreads();
    red[t] = fmaxf(sc[t], sc[t + 256]);
    __syncthreads();
    for (int st = 128; st > 0; st >>= 1) {
        if (t < st) red[t] = fmaxf(red[t], red[t + st]);
        __syncthreads();
    }
    float mx = red[0];
    __syncthreads();
    float e0 = expf(sc[t] - mx), e1 = expf(sc[t + 256] - mx);
    sc[t] = e0; sc[t + 256] = e1;
    red[t] = e0 + e1;
    __syncthreads();
    for (int st = 128; st > 0; st >>= 1) {
        if (t < st) red[t] += red[t + st];
        __syncthreads();
    }
    float inv = 1.f / red[0];
    float acc = 0.f;
    for (int m = 0; m < M_; m++) acc += sc[m] * mem[(size_t)m * C_ + t];
    float mr2 = acc * inv + ig[t];
    g_gate[b * C_ + t] = 1.f / (1.f + expf(-mr2));
}

// ---------------- K2p: P[m][o] = W2[o,:] . mem[m,:] ----------------
__global__ void k_pmat(const float* __restrict__ mem, const float* __restrict__ fw) {
    __shared__ float row[C_];
    int m = blockIdx.x, o = threadIdx.x;
    row[o] = mem[(size_t)m * C_ + o];
    __syncthreads();
    const float* wr = fw + (size_t)o * 512 + 256;
    float a = 0.f;
    for (int c = 0; c < C_; c += 4) {
        float4 w4 = *(const float4*)(wr + c);
        a += w4.x * row[c] + w4.y * row[c + 1] + w4.z * row[c + 2] + w4.w * row[c + 3];
    }
    g_P[m * C_ + o] = a;
}

// ---------------- K3: main fused kernel ----------------
// 256 threads, 1 block/SM. Tile: 128 px x 64 m (or oc). Thread: 4 px x 8 m.
#define TPX 128
#define XS_ST 132
#define MS_ST 68
#define OFF_XS 0
#define OFF_MS (OFF_XS + 256 * XS_ST)    /* 33792 */
#define OFF_GS (OFF_MS + 256 * MS_ST)    /* 51200 */
#define OFF_BS (OFF_GS + 256)
#define OFF_A0 (OFF_BS + 256)
#define OFF_A1 (OFF_A0 + 128)
#define OFF_I0 (OFF_A1 + 128)
#define OFF_I1 (OFF_I0 + 128)
#define SMEM_FLOATS (OFF_I1 + 128)       /* 52224 */
#define SMEM_MAIN (SMEM_FLOATS * 4)      /* 208896 */

// 256 c-steps of: Xs float4 + 2 broadcast ulonglong2 from swizzled Ms + 16 fma2
static __device__ __forceinline__ void tile_fma(const float* __restrict__ Xs,
                                                const float* __restrict__ Ms,
                                                int px0, int mg0, U64* acc) {
    #pragma unroll 2
    for (int c0 = 0; c0 < 256; c0 += 8) {
        const int mbase = mg0 ^ (8 * ((c0 >> 3) & 7));   // row swizzle (period 8 in c)
        #pragma unroll
        for (int u = 0; u < 8; u++) {
            const int c = c0 + u;
            float4 f4 = *(const float4*)(Xs + c * XS_ST + px0);
            U64 fd0 = dupf(f4.x), fd1 = dupf(f4.y), fd2 = dupf(f4.z), fd3 = dupf(f4.w);
            const float* mrow = Ms + c * MS_ST + mbase;
            ulonglong2 ma = *(const ulonglong2*)(mrow);
            ulonglong2 mb = *(const ulonglong2*)(mrow + 4);
            fma2(acc[0],  fd0, ma.x); fma2(acc[1],  fd0, ma.y); fma2(acc[2],  fd0, mb.x); fma2(acc[3],  fd0, mb.y);
            fma2(acc[4],  fd1, ma.x); fma2(acc[5],  fd1, ma.y); fma2(acc[6],  fd1, mb.x); fma2(acc[7],  fd1, mb.y);
            fma2(acc[8],  fd2, ma.x); fma2(acc[9],  fd2, ma.y); fma2(acc[10], fd2, mb.x); fma2(acc[11], fd2, mb.y);
            fma2(acc[12], fd3, ma.x); fma2(acc[13], fd3, ma.y); fma2(acc[14], fd3, mb.x); fma2(acc[15], fd3, mb.y);
        }
    }
}

__global__ void __launch_bounds__(256, 1) k_main(
    const float* __restrict__ img, const float* __restrict__ mem,
    const float* __restrict__ fw, const float* __restrict__ fb)
{
    extern __shared__ float sm[];
    float* Xs = sm + OFF_XS;   // [256 c][132] feature tile (pixel-minor)
    float* Ms = sm + OFF_MS;   // [256 c][68]  mem / W1 chunk, col-major, row-swizzled
    float* gS = sm + OFF_GS;
    float* bS = sm + OFF_BS;
    float* A0 = sm + OFF_A0;
    float* A1 = sm + OFF_A1;
    int*   I0 = (int*)(sm + OFF_I0);
    int*   I1 = (int*)(sm + OFF_I1);
    // top-2 candidate arrays alias Ms (used between score and fusion phases)
    float* cV0 = Ms;
    float* cV1 = Ms + 1024;
    int*   cI0 = (int*)(Ms + 2048);
    int*   cI1 = (int*)(Ms + 3072);

    const int t    = threadIdx.x;
    const int b    = blockIdx.x >> 5;
    const int p0   = (blockIdx.x & 31) * TPX;
    const int px0  = 4 * (t & 31);       // pixel quad
    const int mgrp = t >> 5;             // 0..7
    const int mg0  = 8 * mgrp;           // m (or oc) group base
    const int sw_t = 8 * ((t >> 3) & 7); // store-side swizzle for column t

    gS[t] = g_gate[b * C_ + t];
    bS[t] = fb[t];

    const float* ib = img + (size_t)b * C_ * HW_ + p0;
    for (int i = t; i < 256 * TPX; i += 256) {
        int c = i >> 7, px = i & 127;
        Xs[c * XS_ST + px] = ib[(size_t)c * HW_ + px];
    }
    __syncthreads();

    float v0[4], v1[4];
    int bi0[4], bi1[4];
    #pragma unroll
    for (int i = 0; i < 4; i++) { v0[i] = -3.402823466e38f; v1[i] = -3.402823466e38f; bi0[i] = 0; bi1[i] = 0; }

    // ========== scores X.memT + running top-2 ==========
    for (int mc = 0; mc < M_; mc += 64) {
        // stage 64 mem rows, transposed into Ms: thread t owns column c=t
        {
            const float* src = mem + (size_t)mc * C_ + t;
            float* dst = Ms + t * MS_ST;
            #pragma unroll 8
            for (int r = 0; r < 64; r++) dst[r ^ sw_t] = src[(size_t)r * C_];
        }
        __syncthreads();

        U64 acc[16];
        #pragma unroll
        for (int k = 0; k < 16; k++) acc[k] = 0ULL;
        tile_fma(Xs, Ms, px0, mg0, acc);

        #pragma unroll
        for (int i = 0; i < 4; i++) {
            #pragma unroll
            for (int j = 0; j < 4; j++) {
                float lo, hi; unpk(acc[i * 4 + j], lo, hi);
                int ml = mc + mg0 + 2 * j;
                if (lo > v0[i]) { v1[i] = v0[i]; bi1[i] = bi0[i]; v0[i] = lo; bi0[i] = ml; }
                else if (lo > v1[i]) { v1[i] = lo; bi1[i] = ml; }
                if (hi > v0[i]) { v1[i] = v0[i]; bi1[i] = bi0[i]; v0[i] = hi; bi0[i] = ml + 1; }
                else if (hi > v1[i]) { v1[i] = hi; bi1[i] = ml + 1; }
            }
        }
        __syncthreads();
    }

    // publish per-group candidates (into Ms alias region) + gate-scale Xs
    #pragma unroll
    for (int i = 0; i < 4; i++) {
        int p = px0 + i;
        cV0[mgrp * 128 + p] = v0[i];  cI0[mgrp * 128 + p] = bi0[i];
        cV1[mgrp * 128 + p] = v1[i];  cI1[mgrp * 128 + p] = bi1[i];
    }
    for (int i = t; i < 256 * TPX; i += 256) {
        int c = i >> 7, px = i & 127;
        Xs[c * XS_ST + px] *= gS[c];
    }
    __syncthreads();

    // merge 8 group candidates per pixel -> softmax(top2)
    if (t < TPX) {
        float b0 = -3.402823466e38f, b1 = -3.402823466e38f;
        int j0 = 0, j1 = 0;
        #pragma unroll
        for (int g = 0; g < 8; g++) {
            float v = cV0[g * 128 + t]; int id = cI0[g * 128 + t];
            if (v > b0 || (v == b0 && id < j0)) { b1 = b0; j1 = j0; b0 = v; j0 = id; }
            else if (v > b1 || (v == b1 && id < j1)) { b1 = v; j1 = id; }
            v = cV1[g * 128 + t]; id = cI1[g * 128 + t];
            if (v > b0 || (v == b0 && id < j0)) { b1 = b0; j1 = j0; b0 = v; j0 = id; }
            else if (v > b1 || (v == b1 && id < j1)) { b1 = v; j1 = id; }
        }
        float e = expf(b1 - b0);
        float a0 = 1.f / (1.f + e);
        A0[t] = a0; A1[t] = e * a0; I0[t] = j0; I1[t] = j1;
    }
    __syncthreads();

    // hoist per-pixel attention into registers
    float a0r[4], a1r[4]; int i0r[4], i1r[4];
    #pragma unroll
    for (int i = 0; i < 4; i++) {
        int p = px0 + i;
        a0r[i] = A0[p]; a1r[i] = A1[p]; i0r[i] = I0[p]; i1r[i] = I1[p];
    }

    // ========== fusion: x = leaky(W1.(gate*X) + a0*P[i0] + a1*P[i1] + b) ==========
    for (int oc = 0; oc < C_; oc += 64) {
        {
            const float* src = fw + (size_t)oc * 512 + t;
            float* dst = Ms + t * MS_ST;
            #pragma unroll 8
            for (int r = 0; r < 64; r++) dst[r ^ sw_t] = src[(size_t)r * 512];
        }
        __syncthreads();

        U64 acc[16];
        #pragma unroll
        for (int k = 0; k < 16; k++) acc[k] = 0ULL;
        tile_fma(Xs, Ms, px0, mg0, acc);

        #pragma unroll
        for (int i = 0; i < 4; i++) {
            const float* P0 = g_P + (size_t)i0r[i] * C_ + oc + mg0;
            const float* P1 = g_P + (size_t)i1r[i] * C_ + oc + mg0;
            float4 q0a = *(const float4*)P0, q0b = *(const float4*)(P0 + 4);
            float4 q1a = *(const float4*)P1, q1b = *(const float4*)(P1 + 4);
            float a0 = a0r[i], a1 = a1r[i];
            float pv[8];
            pv[0] = a0 * q0a.x + a1 * q1a.x;  pv[1] = a0 * q0a.y + a1 * q1a.y;
            pv[2] = a0 * q0a.z + a1 * q1a.z;  pv[3] = a0 * q0a.w + a1 * q1a.w;
            pv[4] = a0 * q0b.x + a1 * q1b.x;  pv[5] = a0 * q0b.y + a1 * q1b.y;
            pv[6] = a0 * q0b.z + a1 * q1b.z;  pv[7] = a0 * q0b.w + a1 * q1b.w;
            float* xout = g_x + ((size_t)b * C_ + oc + mg0) * HW_ + p0 + px0 + i;
            #pragma unroll
            for (int j = 0; j < 4; j++) {
                float lo, hi; unpk(acc[i * 4 + j], lo, hi);
                float vl = lo + pv[2 * j]     + bS[oc + mg0 + 2 * j];
                float vh = hi + pv[2 * j + 1] + bS[oc + mg0 + 2 * j + 1];
                vl = (vl > 0.f) ? vl : 0.2f * vl;
                vh = (vh > 0.f) ? vh : 0.2f * vh;
                xout[(size_t)(2 * j) * HW_] = vl;
                xout[(size_t)(2 * j + 1) * HW_] = vh;
            }
        }
        __syncthreads();
    }
}

// ---------------- K4: depthwise dilated 3x3 (d=2) + bias + leaky ----------------
__global__ void k_dw(const float* __restrict__ dw, const float* __restrict__ db,
                     float* __restrict__ out) {
    __shared__ float sx[4096];
    __shared__ float w[9];
    int bc = blockIdx.x;
    int c = bc & 255;
    int t = threadIdx.x;
    const float* xin = g_x + (size_t)bc * HW_;
    for (int i = t; i < 4096; i += 256) sx[i] = xin[i];
    if (t < 9) w[t] = dw[c * 9 + t];
    __syncthreads();
    float bias = db[c];
    for (int p = t; p < 4096; p += 256) {
        int y = p >> 6, x = p & 63;
        float s = bias;
        #pragma unroll
        for (int ky = 0; ky < 3; ky++) {
            int iy = y + 2 * ky - 2;
            if ((unsigned)iy < 64u) {
                #pragma unroll
                for (int kx = 0; kx < 3; kx++) {
                    int ix = x + 2 * kx - 2;
                    if ((unsigned)ix < 64u) s += w[ky * 3 + kx] * sx[(iy << 6) + ix];
                }
            }
        }
        out[(size_t)bc * HW_ + p] = (s > 0.f) ? s : 0.2f * s;
    }
}

extern "C" void kernel_launch(void* const* d_in, const int* in_sizes, int n_in,
                              void* d_out, int out_size) {
    const float* img = (const float*)d_in[0];
    const float* mem = (const float*)d_in[1];
    const float* fw  = (const float*)d_in[2];
    const float* fb  = (const float*)d_in[3];
    const float* dw  = (const float*)d_in[4];
    const float* db  = (const float*)d_in[5];
    float* out = (float*)d_out;

    cudaFuncSetAttribute(k_main, cudaFuncAttributeMaxDynamicSharedMemorySize, SMEM_MAIN);

    k_mean<<<B_ * C_, 256>>>(img);
    k_global<<<B_, 256>>>(mem);
    k_pmat<<<M_, 256>>>(mem, fw);
    k_main<<<B_ * (HW_ / TPX), 256, SMEM_MAIN>>>(img, mem, fw, fb);
    k_dw<<<B_ * C_, 256>>>(dw, db, out);
}

// round 5
// speedup vs baseline: 2.1387x; 1.4007x over previous
#include <cuda_runtime.h>
#include <cuda_bf16.h>
#include <cstdint>

#define B_  8
#define C_  256
#define HW_ 4096
#define M_  512

// ---------------- device scratch ----------------
__device__ float g_IG[B_ * C_];
__device__ float g_gate[B_ * C_];
__device__ float g_P[M_ * C_];                    // P[m][o] = sum_c W2[o][c]*mem[m][c]
__device__ float g_x[(size_t)B_ * C_ * HW_];      // pre-depthwise activations
__device__ unsigned char g_memB[8 * 65536];       // pre-permuted bf16 h/l fragment images of memory (8 chunks)

// ---------------- helpers ----------------
static __device__ __forceinline__ void mma_bf16(float* c,
    uint32_t a0, uint32_t a1, uint32_t a2, uint32_t a3, uint32_t b0, uint32_t b1) {
    asm("mma.sync.aligned.m16n8k16.row.col.f32.bf16.bf16.f32 "
        "{%0,%1,%2,%3}, {%4,%5,%6,%7}, {%8,%9}, {%0,%1,%2,%3};"
        : "+f"(c[0]), "+f"(c[1]), "+f"(c[2]), "+f"(c[3])
        : "r"(a0), "r"(a1), "r"(a2), "r"(a3), "r"(b0), "r"(b1));
}
static __device__ __forceinline__ void split_bf16(float v, unsigned short& hb, unsigned short& lb) {
    __nv_bfloat16 h = __float2bfloat16_rn(v);
    __nv_bfloat16 l = __float2bfloat16_rn(v - __bfloat162float(h));
    hb = *(unsigned short*)&h;
    lb = *(unsigned short*)&l;
}

// ---------------- K1: per-(b,c) spatial mean ----------------
__global__ void k_mean(const float* __restrict__ img) {
    __shared__ float red[256];
    int bc = blockIdx.x;
    const float4* p = (const float4*)(img + (size_t)bc * HW_);
    float s = 0.f;
    for (int i = threadIdx.x; i < HW_ / 4; i += 256) {
        float4 v = p[i];
        s += (v.x + v.y) + (v.z + v.w);
    }
    red[threadIdx.x] = s;
    __syncthreads();
    for (int st = 128; st > 0; st >>= 1) {
        if (threadIdx.x < st) red[threadIdx.x] += red[threadIdx.x + st];
        __syncthreads();
    }
    if (threadIdx.x == 0) g_IG[bc] = red[0] * (1.f / (float)HW_);
}

// ---------------- K2: global path -> gate ----------------
__global__ void k_global(const float* __restrict__ mem) {
    __shared__ float sc[M_];
    __shared__ float ig[C_];
    __shared__ float red[256];
    int b = blockIdx.x, t = threadIdx.x;
    ig[t] = g_IG[b * C_ + t];
    __syncthreads();
    #pragma unroll
    for (int r = 0; r < 2; r++) {
        int m = t + r * 256;
        const float* mr = mem + (size_t)m * C_;
        float a = 0.f;
        for (int c = 0; c < C_; c += 4) {
            float4 mv = *(const float4*)(mr + c);
            a += ig[c] * mv.x + ig[c + 1] * mv.y + ig[c + 2] * mv.z + ig[c + 3] * mv.w;
        }
        sc[m] = a;
    }
    __syncthreads();
    red[t] = fmaxf(sc[t], sc[t + 256]);
    __syncthreads();
    for (int st = 128; st > 0; st >>= 1) {
        if (t < st) red[t] = fmaxf(red[t], red[t + st]);
        __syncthreads();
    }
    float mx = red[0];
    __syncthreads();
    float e0 = expf(sc[t] - mx), e1 = expf(sc[t + 256] - mx);
    sc[t] = e0; sc[t + 256] = e1;
    red[t] = e0 + e1;
    __syncthreads();
    for (int st = 128; st > 0; st >>= 1) {
        if (t < st) red[t] += red[t + st];
        __syncthreads();
    }
    float inv = 1.f / red[0];
    float acc = 0.f;
    for (int m = 0; m < M_; m++) acc += sc[m] * mem[(size_t)m * C_ + t];
    float mr2 = acc * inv + ig[t];
    g_gate[b * C_ + t] = 1.f / (1.f + expf(-mr2));
}

// ---------------- K2p: P[m][o] = W2[o,:] . mem[m,:] ----------------
__global__ void k_pmat(const float* __restrict__ mem, const float* __restrict__ fw) {
    __shared__ float row[C_];
    int m = blockIdx.x, o = threadIdx.x;
    row[o] = mem[(size_t)m * C_ + o];
    __syncthreads();
    const float* wr = fw + (size_t)o * 512 + 256;
    float a = 0.f;
    for (int c = 0; c < C_; c += 4) {
        float4 w4 = *(const float4*)(wr + c);
        a += w4.x * row[c] + w4.y * row[c + 1] + w4.z * row[c + 2] + w4.w * row[c + 3];
    }
    g_P[m * C_ + o] = a;
}

// ---------------- K2m: pre-permute memory into mma B-fragment chunk images ----------------
// chunk ch = 64 m-rows. slot(nt, ks, ln) 16B = [b0h | b1h | b0l | b1l]
__global__ void k_prep(const float* __restrict__ mem) {
    int m = blockIdx.x, c = threadIdx.x;
    float v = mem[(size_t)m * C_ + c];
    unsigned short hb, lb;
    split_bf16(v, hb, lb);
    int ch = m >> 6;
    int nt = (m & 63) >> 3, n = m & 7;
    int ks = c >> 4, kin = c & 15;
    int ln = n * 4 + ((kin & 7) >> 1);
    int slot = (nt * 16 + ks) * 32 + ln;
    int off = ((kin >> 3) ? 4 : 0) + (kin & 1) * 2;
    unsigned char* base = g_memB + ch * 65536 + slot * 16;
    *(uint16_t*)(base + off) = hb;
    *(uint16_t*)(base + off + 8) = lb;
}

// ---------------- K3: main fused kernel (mma.sync bf16) ----------------
// smem: A frags [0,131072): H 64KB + L 64KB; B frags [131072,196608); small [196608,200704)
#define OFF_B   131072
#define OFF_SM  196608
#define SMEM_MAIN 200704
#define NCHUNK 12

#define UPD(slot, val, idx) do { float _v = (val); \
    if (_v > v0[slot]) { v1[slot] = v0[slot]; i1[slot] = i0[slot]; v0[slot] = _v; i0[slot] = (idx); } \
    else if (_v > v1[slot]) { v1[slot] = _v; i1[slot] = (idx); } } while (0)

__global__ void __launch_bounds__(256, 1) k_main(
    const float* __restrict__ img, const float* __restrict__ fw, const float* __restrict__ fb)
{
    extern __shared__ unsigned char sm[];
    const int t  = threadIdx.x;
    const int b  = blockIdx.x >> 5;
    const int p0 = (blockIdx.x & 31) * 128;
    const int w  = t >> 5;           // warp 0..7
    const int ln = t & 31;
    const int wr = w >> 1;           // px group: rows [32*wr, 32*wr+32)
    const int wc = w & 1;            // n group:  cols [32*wc, 32*wc+32)

    float* A0s = (float*)(sm + OFF_SM);
    float* A1s = (float*)(sm + OFF_SM + 512);
    int*   I0s = (int*)  (sm + OFF_SM + 1024);
    int*   I1s = (int*)  (sm + OFF_SM + 1536);
    float* gSs = (float*)(sm + OFF_SM + 2048);
    float* bSs = (float*)(sm + OFF_SM + 3072);

    gSs[t] = g_gate[b * C_ + t];
    bSs[t] = fb[t];

    // ---- stage A once: 128 px x 256 c, split bf16, fragment-permuted ----
    {
        const float* ib = img + (size_t)b * C_ * HW_ + p0;
        for (int i = t; i < 128 * 256; i += 256) {
            int px = i & 127, c = i >> 7;
            float v = ib[(size_t)c * HW_ + px];
            unsigned short hb, lb;
            split_bf16(v, hb, lb);
            int mtg = px >> 4, r = px & 15;
            int ks = c >> 4, kin = c & 15;
            int lnA = (r & 7) * 4 + ((kin & 7) >> 1);
            int slot = (mtg * 16 + ks) * 32 + lnA;
            int off = ((kin >> 3) * 2 + (r >> 3)) * 4 + (kin & 1) * 2;
            *(uint16_t*)(sm + slot * 16 + off) = hb;
            *(uint16_t*)(sm + 65536 + slot * 16 + off) = lb;
        }
    }

    float v0[4], v1[4];
    int   i0[4], i1[4];
    #pragma unroll
    for (int s = 0; s < 4; s++) { v0[s] = -3.402823466e38f; v1[s] = -3.402823466e38f; i0[s] = 0; i1[s] = 0; }

    const uint4* Afr = (const uint4*)sm;             // H at idx 0.., L at idx +4096
    const uint4* Bfr = (const uint4*)(sm + OFF_B);

    for (int n = 0; n < NCHUNK; n++) {
        __syncthreads();   // B region free (prev readers/writers done)

        // ---- stage B chunk ----
        if (n < 8) {
            const uint4* src = (const uint4*)(g_memB + n * 65536);
            uint4* dst = (uint4*)(sm + OFF_B);
            #pragma unroll 4
            for (int i = t; i < 4096; i += 256) dst[i] = src[i];
        } else {
            int oc0 = (n - 8) * 64;
            for (int i = t; i < 64 * 256; i += 256) {
                int c = i & 255, r = i >> 8;
                float wv = fw[(size_t)(oc0 + r) * 512 + c] * gSs[c];
                unsigned short hb, lb;
                split_bf16(wv, hb, lb);
                int nt = r >> 3, nn = r & 7;
                int ks = c >> 4, kin = c & 15;
                int lnB = nn * 4 + ((kin & 7) >> 1);
                int slot = (nt * 16 + ks) * 32 + lnB;
                int off = ((kin >> 3) ? 4 : 0) + (kin & 1) * 2;
                unsigned char* bp = sm + OFF_B + slot * 16;
                *(uint16_t*)(bp + off) = hb;
                *(uint16_t*)(bp + off + 8) = lb;
            }
        }
        __syncthreads();

        // ---- MMA: warp tile 32 px x 32 n, K=256, 3 passes ----
        float acc[2][4][4];
        #pragma unroll
        for (int mt = 0; mt < 2; mt++)
            #pragma unroll
            for (int nt = 0; nt < 4; nt++)
                #pragma unroll
                for (int q = 0; q < 4; q++) acc[mt][nt][q] = 0.f;

        const int abase0 = ((wr * 2 + 0) * 16) * 32 + ln;
        const int abase1 = ((wr * 2 + 1) * 16) * 32 + ln;
        #pragma unroll 4
        for (int ks = 0; ks < 16; ks++) {
            uint4 ah0 = Afr[abase0 + ks * 32];
            uint4 al0 = Afr[abase0 + ks * 32 + 4096];
            uint4 ah1 = Afr[abase1 + ks * 32];
            uint4 al1 = Afr[abase1 + ks * 32 + 4096];
            #pragma unroll
            for (int nt = 0; nt < 4; nt++) {
                uint4 bv = Bfr[((wc * 4 + nt) * 16 + ks) * 32 + ln];
                mma_bf16(acc[0][nt], ah0.x, ah0.y, ah0.z, ah0.w, bv.x, bv.y);
                mma_bf16(acc[0][nt], ah0.x, ah0.y, ah0.z, ah0.w, bv.z, bv.w);
                mma_bf16(acc[0][nt], al0.x, al0.y, al0.z, al0.w, bv.x, bv.y);
                mma_bf16(acc[1][nt], ah1.x, ah1.y, ah1.z, ah1.w, bv.x, bv.y);
                mma_bf16(acc[1][nt], ah1.x, ah1.y, ah1.z, ah1.w, bv.z, bv.w);
                mma_bf16(acc[1][nt], al1.x, al1.y, al1.z, al1.w, bv.x, bv.y);
            }
        }
        __syncthreads();   // all warps done with B; B region reusable as scratch

        if (n < 8) {
            // ---- scores epilogue: running top-2 per pixel-row (registers) ----
            int mcol = n * 64 + wc * 32 + (ln & 3) * 2;
            #pragma unroll
            for (int mt = 0; mt < 2; mt++)
                #pragma unroll
                for (int nt = 0; nt < 4; nt++) {
                    int mi = mcol + nt * 8;
                    UPD(mt * 2 + 0, acc[mt][nt][0], mi);
                    UPD(mt * 2 + 0, acc[mt][nt][1], mi + 1);
                    UPD(mt * 2 + 1, acc[mt][nt][2], mi);
                    UPD(mt * 2 + 1, acc[mt][nt][3], mi + 1);
                }

            if (n == 7) {
                // publish per-lane candidates into B-scratch, then merge
                float4* scr = (float4*)(sm + OFF_B);
                #pragma unroll
                for (int mt = 0; mt < 2; mt++)
                    #pragma unroll
                    for (int hf = 0; hf < 2; hf++) {
                        int s = mt * 2 + hf;
                        int r = wr * 32 + mt * 16 + (ln >> 2) + hf * 8;
                        scr[r * 8 + wc * 4 + (ln & 3)] =
                            make_float4(v0[s], v1[s], __int_as_float(i0[s]), __int_as_float(i1[s]));
                    }
                __syncthreads();
                if (t < 128) {
                    float bv0 = -3.402823466e38f, bv1 = -3.402823466e38f;
                    int bj0 = 0, bj1 = 0;
                    #pragma unroll
                    for (int g = 0; g < 8; g++) {
                        float4 cd = scr[t * 8 + g];
                        float cv = cd.x; int cj = __float_as_int(cd.z);
                        if (cv > bv0 || (cv == bv0 && cj < bj0)) { bv1 = bv0; bj1 = bj0; bv0 = cv; bj0 = cj; }
                        else if (cv > bv1 || (cv == bv1 && cj < bj1)) { bv1 = cv; bj1 = cj; }
                        cv = cd.y; cj = __float_as_int(cd.w);
                        if (cv > bv0 || (cv == bv0 && cj < bj0)) { bv1 = bv0; bj1 = bj0; bv0 = cv; bj0 = cj; }
                        else if (cv > bv1 || (cv == bv1 && cj < bj1)) { bv1 = cv; bj1 = cj; }
                    }
                    float e = expf(bv1 - bv0);
                    float a0 = 1.f / (1.f + e);
                    A0s[t] = a0; A1s[t] = e * a0; I0s[t] = bj0; I1s[t] = bj1;
                }
            }
        } else {
            // ---- fusion epilogue: + a0*P[i0] + a1*P[i1] + bias, leaky, transpose, store ----
            int oc0 = (n - 8) * 64;
            float* xp = (float*)(sm + OFF_B);   // [64 oc][stride 132] px
            #pragma unroll
            for (int mt = 0; mt < 2; mt++) {
                int rb = wr * 32 + mt * 16 + (ln >> 2);
                #pragma unroll
                for (int hf = 0; hf < 2; hf++) {
                    int r = rb + hf * 8;
                    float a0 = A0s[r], a1 = A1s[r];
                    const float* P0 = g_P + (size_t)I0s[r] * C_ + oc0;
                    const float* P1 = g_P + (size_t)I1s[r] * C_ + oc0;
                    #pragma unroll
                    for (int nt = 0; nt < 4; nt++) {
                        int ocl = wc * 32 + nt * 8 + (ln & 3) * 2;
                        float2 q0 = *(const float2*)(P0 + ocl);
                        float2 q1 = *(const float2*)(P1 + ocl);
                        float vx = acc[mt][nt][hf * 2 + 0] + a0 * q0.x + a1 * q1.x + bSs[oc0 + ocl];
                        float vy = acc[mt][nt][hf * 2 + 1] + a0 * q0.y + a1 * q1.y + bSs[oc0 + ocl + 1];
                        vx = (vx > 0.f) ? vx : 0.2f * vx;
                        vy = (vy > 0.f) ? vy : 0.2f * vy;
                        xp[ocl * 132 + r] = vx;
                        xp[(ocl + 1) * 132 + r] = vy;
                    }
                }
            }
            __syncthreads();
            float* xo = g_x + ((size_t)b * C_ + oc0) * HW_ + p0;
            #pragma unroll 4
            for (int i = t; i < 64 * 128; i += 256) {
                int oc = i >> 7, px = i & 127;
                xo[(size_t)oc * HW_ + px] = xp[oc * 132 + px];
            }
        }
    }
}

// ---------------- K4: depthwise dilated 3x3 (d=2) + bias + leaky ----------------
__global__ void k_dw(const float* __restrict__ dw, const float* __restrict__ db,
                     float* __restrict__ out) {
    __shared__ float sx[4096];
    __shared__ float w[9];
    int bc = blockIdx.x;
    int c = bc & 255;
    int t = threadIdx.x;
    const float* xin = g_x + (size_t)bc * HW_;
    for (int i = t; i < 4096; i += 256) sx[i] = xin[i];
    if (t < 9) w[t] = dw[c * 9 + t];
    __syncthreads();
    float bias = db[c];
    for (int p = t; p < 4096; p += 256) {
        int y = p >> 6, x = p & 63;
        float s = bias;
        #pragma unroll
        for (int ky = 0; ky < 3; ky++) {
            int iy = y + 2 * ky - 2;
            if ((unsigned)iy < 64u) {
                #pragma unroll
                for (int kx = 0; kx < 3; kx++) {
                    int ix = x + 2 * kx - 2;
                    if ((unsigned)ix < 64u) s += w[ky * 3 + kx] * sx[(iy << 6) + ix];
                }
            }
        }
        out[(size_t)bc * HW_ + p] = (s > 0.f) ? s : 0.2f * s;
    }
}

extern "C" void kernel_launch(void* const* d_in, const int* in_sizes, int n_in,
                              void* d_out, int out_size) {
    const float* img = (const float*)d_in[0];
    const float* mem = (const float*)d_in[1];
    const float* fw  = (const float*)d_in[2];
    const float* fb  = (const float*)d_in[3];
    const float* dw  = (const float*)d_in[4];
    const float* db  = (const float*)d_in[5];
    float* out = (float*)d_out;

    cudaFuncSetAttribute(k_main, cudaFuncAttributeMaxDynamicSharedMemorySize, SMEM_MAIN);

    k_mean<<<B_ * C_, 256>>>(img);
    k_global<<<B_, 256>>>(mem);
    k_pmat<<<M_, 256>>>(mem, fw);
    k_prep<<<M_, 256>>>(mem);
    k_main<<<B_ * (HW_ / 128), 256, SMEM_MAIN>>>(img, fw, fb);
    k_dw<<<B_ * C_, 256>>>(dw, db, out);
}

// round 7
// speedup vs baseline: 2.4829x; 1.1609x over previous
#include <cuda_runtime.h>
#include <cuda_bf16.h>
#include <cstdint>

#define B_  8
#define C_  256
#define HW_ 4096
#define M_  512

// ---------------- device scratch ----------------
__device__ float g_IG[B_ * C_];
__device__ float g_gate[B_ * C_];
__device__ float g_P[M_ * C_];                    // P[m][o] = sum_c W2[o][c]*mem[m][c]
__device__ float g_x[(size_t)B_ * C_ * HW_];      // pre-depthwise activations
__device__ unsigned char g_memB[8 * 65536];       // pre-built B fragment images: memory (8 chunks)
__device__ unsigned char g_fwB[B_ * 4 * 65536];   // pre-built B fragment images: gated fusion_w (per batch)

// ---------------- helpers ----------------
static __device__ __forceinline__ void mma_bf16(float* c,
    uint32_t a0, uint32_t a1, uint32_t a2, uint32_t a3, uint32_t b0, uint32_t b1) {
    asm("mma.sync.aligned.m16n8k16.row.col.f32.bf16.bf16.f32 "
        "{%0,%1,%2,%3}, {%4,%5,%6,%7}, {%8,%9}, {%0,%1,%2,%3};"
        : "+f"(c[0]), "+f"(c[1]), "+f"(c[2]), "+f"(c[3])
        : "r"(a0), "r"(a1), "r"(a2), "r"(a3), "r"(b0), "r"(b1));
}
static __device__ __forceinline__ void split_bf16(float v, unsigned short& hb, unsigned short& lb) {
    __nv_bfloat16 h = __float2bfloat16_rn(v);
    __nv_bfloat16 l = __float2bfloat16_rn(v - __bfloat162float(h));
    hb = *(unsigned short*)&h;
    lb = *(unsigned short*)&l;
}
static __device__ __forceinline__ uint32_t pk(unsigned short a, unsigned short b) {
    return (uint32_t)a | ((uint32_t)b << 16);
}

// ---------------- K1: per-(b,c) spatial mean ----------------
__global__ void k_mean(const float* __restrict__ img) {
    __shared__ float red[256];
    int bc = blockIdx.x;
    const float4* p = (const float4*)(img + (size_t)bc * HW_);
    float s = 0.f;
    for (int i = threadIdx.x; i < HW_ / 4; i += 256) {
        float4 v = p[i];
        s += (v.x + v.y) + (v.z + v.w);
    }
    red[threadIdx.x] = s;
    __syncthreads();
    for (int st = 128; st > 0; st >>= 1) {
        if (threadIdx.x < st) red[threadIdx.x] += red[threadIdx.x + st];
        __syncthreads();
    }
    if (threadIdx.x == 0) g_IG[bc] = red[0] * (1.f / (float)HW_);
}

// ---------------- K2: global path -> gate ----------------
__global__ void k_global(const float* __restrict__ mem) {
    __shared__ float sc[M_];
    __shared__ float ig[C_];
    __shared__ float red[256];
    int b = blockIdx.x, t = threadIdx.x;
    ig[t] = g_IG[b * C_ + t];
    __syncthreads();
    #pragma unroll
    for (int r = 0; r < 2; r++) {
        int m = t + r * 256;
        const float* mr = mem + (size_t)m * C_;
        float a = 0.f;
        for (int c = 0; c < C_; c += 4) {
            float4 mv = *(const float4*)(mr + c);
            a += ig[c] * mv.x + ig[c + 1] * mv.y + ig[c + 2] * mv.z + ig[c + 3] * mv.w;
        }
        sc[m] = a;
    }
    __syncthreads();
    red[t] = fmaxf(sc[t], sc[t + 256]);
    __syncthreads();
    for (int st = 128; st > 0; st >>= 1) {
        if (t < st) red[t] = fmaxf(red[t], red[t + st]);
        __syncthreads();
    }
    float mx = red[0];
    __syncthreads();
    float e0 = expf(sc[t] - mx), e1 = expf(sc[t + 256] - mx);
    sc[t] = e0; sc[t + 256] = e1;
    red[t] = e0 + e1;
    __syncthreads();
    for (int st = 128; st > 0; st >>= 1) {
        if (t < st) red[t] += red[t + st];
        __syncthreads();
    }
    float inv = 1.f / red[0];
    float acc = 0.f;
    for (int m = 0; m < M_; m++) acc += sc[m] * mem[(size_t)m * C_ + t];
    float mr2 = acc * inv + ig[t];
    g_gate[b * C_ + t] = 1.f / (1.f + expf(-mr2));
}

// ---------------- K2p: P[m][o] = W2[o,:] . mem[m,:] ----------------
__global__ void k_pmat(const float* __restrict__ mem, const float* __restrict__ fw) {
    __shared__ float row[C_];
    int m = blockIdx.x, o = threadIdx.x;
    row[o] = mem[(size_t)m * C_ + o];
    __syncthreads();
    const float* wr = fw + (size_t)o * 512 + 256;
    float a = 0.f;
    for (int c = 0; c < C_; c += 4) {
        float4 w4 = *(const float4*)(wr + c);
        a += w4.x * row[c] + w4.y * row[c + 1] + w4.z * row[c + 2] + w4.w * row[c + 3];
    }
    g_P[m * C_ + o] = a;
}

// ---------------- K2m: memory -> B fragment images (whole-slot writes) ----------------
__global__ void k_prep(const float* __restrict__ mem) {
    int u = blockIdx.x * 256 + threadIdx.x;   // 8192 = 512 m x 16 ks
    int ks = u >> 9;
    int m  = u & 511;
    const float* mr = mem + (size_t)m * C_ + ks * 16;
    unsigned short hs[16], ls[16];
    #pragma unroll
    for (int kin = 0; kin < 16; kin++) split_bf16(mr[kin], hs[kin], ls[kin]);
    int ch = m >> 6, rr = m & 63, nt = rr >> 3, nn = rr & 7;
    uint4* dst = (uint4*)(g_memB + ch * 65536) + (nt * 16 + ks) * 32 + nn * 4;
    #pragma unroll
    for (int j = 0; j < 4; j++)
        dst[j] = make_uint4(pk(hs[2*j], hs[2*j+1]), pk(hs[8+2*j], hs[8+2*j+1]),
                            pk(ls[2*j], ls[2*j+1]), pk(ls[8+2*j], ls[8+2*j+1]));
}

// ---------------- K2w: gated fusion_w -> B fragment images per batch ----------------
__global__ void k_prepw(const float* __restrict__ fw) {
    int u = blockIdx.x * 256 + threadIdx.x;   // 32768 = 16 ks x 8 b x 256 r
    int ks = u >> 11;
    int b  = (u >> 8) & 7;
    int r  = u & 255;
    const float* wr = fw + (size_t)r * 512 + ks * 16;
    const float* gt = g_gate + b * C_ + ks * 16;
    unsigned short hs[16], ls[16];
    #pragma unroll
    for (int kin = 0; kin < 16; kin++) split_bf16(wr[kin] * gt[kin], hs[kin], ls[kin]);
    int ch = r >> 6, rr = r & 63, nt = rr >> 3, nn = rr & 7;
    uint4* dst = (uint4*)(g_fwB + (b * 4 + ch) * 65536) + (nt * 16 + ks) * 32 + nn * 4;
    #pragma unroll
    for (int j = 0; j < 4; j++)
        dst[j] = make_uint4(pk(hs[2*j], hs[2*j+1]), pk(hs[8+2*j], hs[8+2*j+1]),
                            pk(ls[2*j], ls[2*j+1]), pk(ls[8+2*j], ls[8+2*j+1]));
}

// ---------------- K3: main fused kernel ----------------
// A half (padded) = 4096*16 + 512*16 = 73728 B
// smem: A_h [0,73728), A_l [73728,147456), B [147456,212992), small [212992,220160)
#define OFF_AL 73728
#define OFF_B  147456
#define OFF_SM 212992
#define SMEM_MAIN 220160
#define NCHUNK 12

#define UPD(slot, val, idx) do { float _v = (val); \
    if (_v > v0[slot]) { v1[slot] = v0[slot]; i1[slot] = i0[slot]; v0[slot] = _v; i0[slot] = (idx); } \
    else if (_v > v1[slot]) { v1[slot] = _v; i1[slot] = (idx); } } while (0)

// padded A slot byte offset: 16B slot + 16B pad per 8 slots (keeps 16B alignment)
static __device__ __forceinline__ uint32_t apad(int s) {
    return ((uint32_t)s << 4) + (((uint32_t)s >> 3) << 4);
}

template<bool P4>
static __device__ __forceinline__ void chunk_mma(const unsigned char* sm,
                                                 int wr, int wc, int ln, float acc[2][4][4]) {
    const uint4* Bfr = (const uint4*)(sm + OFF_B);
    const int sA0 = (wr * 2 + 0) * 512 + ln;
    const int sA1 = (wr * 2 + 1) * 512 + ln;
    #pragma unroll 4
    for (int ks = 0; ks < 16; ks++) {
        int s0 = sA0 + ks * 32, s1 = sA1 + ks * 32;
        uint4 ah0 = *(const uint4*)(sm + apad(s0));
        uint4 al0 = *(const uint4*)(sm + OFF_AL + apad(s0));
        uint4 ah1 = *(const uint4*)(sm + apad(s1));
        uint4 al1 = *(const uint4*)(sm + OFF_AL + apad(s1));
        #pragma unroll
        for (int nt = 0; nt < 4; nt++) {
            uint4 bv = Bfr[((wc * 4 + nt) * 16 + ks) * 32 + ln];
            mma_bf16(acc[0][nt], ah0.x, ah0.y, ah0.z, ah0.w, bv.x, bv.y);
            mma_bf16(acc[0][nt], ah0.x, ah0.y, ah0.z, ah0.w, bv.z, bv.w);
            mma_bf16(acc[0][nt], al0.x, al0.y, al0.z, al0.w, bv.x, bv.y);
            if (P4) mma_bf16(acc[0][nt], al0.x, al0.y, al0.z, al0.w, bv.z, bv.w);
            mma_bf16(acc[1][nt], ah1.x, ah1.y, ah1.z, ah1.w, bv.x, bv.y);
            mma_bf16(acc[1][nt], ah1.x, ah1.y, ah1.z, ah1.w, bv.z, bv.w);
            mma_bf16(acc[1][nt], al1.x, al1.y, al1.z, al1.w, bv.x, bv.y);
            if (P4) mma_bf16(acc[1][nt], al1.x, al1.y, al1.z, al1.w, bv.z, bv.w);
        }
    }
}

__global__ void __launch_bounds__(256, 1) k_main(
    const float* __restrict__ img, const float* __restrict__ fb)
{
    extern __shared__ unsigned char sm[];
    const int t  = threadIdx.x;
    const int b  = blockIdx.x >> 5;
    const int p0 = (blockIdx.x & 31) * 128;
    const int w  = t >> 5;
    const int ln = t & 31;
    const int wr = w >> 1;
    const int wc = w & 1;

    float*  A0s  = (float*)(sm + OFF_SM);
    float*  A1s  = (float*)(sm + OFF_SM + 512);
    int*    I0s  = (int*)  (sm + OFF_SM + 1024);
    int*    I1s  = (int*)  (sm + OFF_SM + 1536);
    float*  bS   = (float*)(sm + OFF_SM + 2048);
    float4* cand = (float4*)(sm + OFF_SM + 3072);

    uint4 st[16];
    uint4* Bd = (uint4*)(sm + OFF_B);

    // LDG chunk 0
    {
        const uint4* src = (const uint4*)g_memB;
        #pragma unroll
        for (int i = 0; i < 16; i++) st[i] = src[t + i * 256];
    }

    // ---- stage A: unit = (row-pair rp, ks); whole 16B slots, padded layout ----
    {
        const float* ib = img + (size_t)b * C_ * HW_ + p0;
        #pragma unroll
        for (int u0 = 0; u0 < 4; u0++) {
            int u = t + u0 * 256;
            int rp = u & 63, ks = u >> 6;
            int pxl = (rp >> 3) * 16 + (rp & 7);
            const float* ibc = ib + (size_t)(ks * 16) * HW_;
            unsigned short hlo[16], llo[16], hhi[16], lhi[16];
            #pragma unroll
            for (int kin = 0; kin < 16; kin++) {
                split_bf16(ibc[(size_t)kin * HW_ + pxl],     hlo[kin], llo[kin]);
                split_bf16(ibc[(size_t)kin * HW_ + pxl + 8], hhi[kin], lhi[kin]);
            }
            int s0 = ((rp >> 3) * 16 + ks) * 32 + (rp & 7) * 4;
            #pragma unroll
            for (int j = 0; j < 4; j++) {
                uint32_t ap = apad(s0 + j);
                *(uint4*)(sm + ap) =
                    make_uint4(pk(hlo[2*j], hlo[2*j+1]), pk(hhi[2*j], hhi[2*j+1]),
                               pk(hlo[8+2*j], hlo[8+2*j+1]), pk(hhi[8+2*j], hhi[8+2*j+1]));
                *(uint4*)(sm + OFF_AL + ap) =
                    make_uint4(pk(llo[2*j], llo[2*j+1]), pk(lhi[2*j], lhi[2*j+1]),
                               pk(llo[8+2*j], llo[8+2*j+1]), pk(lhi[8+2*j], lhi[8+2*j+1]));
            }
        }
    }
    bS[t] = fb[t];

    // STS chunk 0, LDG chunk 1
    #pragma unroll
    for (int i = 0; i < 16; i++) Bd[t + i * 256] = st[i];
    {
        const uint4* src = (const uint4*)(g_memB + 65536);
        #pragma unroll
        for (int i = 0; i < 16; i++) st[i] = src[t + i * 256];
    }
    __syncthreads();

    float v0[4], v1[4];
    int   i0[4], i1[4];
    #pragma unroll
    for (int s = 0; s < 4; s++) { v0[s] = -3.402823466e38f; v1[s] = -3.402823466e38f; i0[s] = 0; i1[s] = 0; }

    for (int n = 0; n < NCHUNK; n++) {
        float acc[2][4][4];
        #pragma unroll
        for (int mt = 0; mt < 2; mt++)
            #pragma unroll
            for (int nt = 0; nt < 4; nt++)
                #pragma unroll
                for (int q = 0; q < 4; q++) acc[mt][nt][q] = 0.f;

        if (n < 8) chunk_mma<true>(sm, wr, wc, ln, acc);
        else       chunk_mma<false>(sm, wr, wc, ln, acc);

        if (n < 8) {
            // ---- scores: running top-2 (registers) ----
            int mcol = n * 64 + wc * 32 + (ln & 3) * 2;
            #pragma unroll
            for (int mt = 0; mt < 2; mt++)
                #pragma unroll
                for (int nt = 0; nt < 4; nt++) {
                    int mi = mcol + nt * 8;
                    UPD(mt * 2 + 0, acc[mt][nt][0], mi);
                    UPD(mt * 2 + 0, acc[mt][nt][1], mi + 1);
                    UPD(mt * 2 + 1, acc[mt][nt][2], mi);
                    UPD(mt * 2 + 1, acc[mt][nt][3], mi + 1);
                }
            if (n == 7) {
                // shfl-merge across the 4 lanes sharing each pixel, publish per-wc candidate
                #pragma unroll
                for (int s = 0; s < 4; s++) {
                    #pragma unroll
                    for (int d = 1; d <= 2; d <<= 1) {
                        float w0 = __shfl_xor_sync(0xFFFFFFFFu, v0[s], d);
                        float w1 = __shfl_xor_sync(0xFFFFFFFFu, v1[s], d);
                        int   j0 = __shfl_xor_sync(0xFFFFFFFFu, i0[s], d);
                        int   j1 = __shfl_xor_sync(0xFFFFFFFFu, i1[s], d);
                        if (w0 > v0[s] || (w0 == v0[s] && j0 < i0[s])) {
                            float ov = v0[s]; int oi = i0[s];
                            v0[s] = w0; i0[s] = j0;
                            if (ov > w1 || (ov == w1 && oi < j1)) { v1[s] = ov; i1[s] = oi; }
                            else { v1[s] = w1; i1[s] = j1; }
                        } else if (w0 > v1[s] || (w0 == v1[s] && j0 < i1[s])) {
                            v1[s] = w0; i1[s] = j0;
                        }
                    }
                    if ((ln & 3) == 0) {
                        int r = wr * 32 + (s >> 1) * 16 + (s & 1) * 8 + (ln >> 2);
                        cand[r * 2 + wc] = make_float4(v0[s], v1[s],
                                                       __int_as_float(i0[s]), __int_as_float(i1[s]));
                    }
                }
            }
        } else {
            // ---- fusion epilogue: + a0*P[i0] + a1*P[i1] + bias, leaky, direct store ----
            int oc0 = (n - 8) * 64;
            #pragma unroll
            for (int mt = 0; mt < 2; mt++)
                #pragma unroll
                for (int hf = 0; hf < 2; hf++) {
                    int r = wr * 32 + mt * 16 + hf * 8 + (ln >> 2);
                    float a0 = A0s[r], a1 = A1s[r];
                    const float* P0 = g_P + (size_t)I0s[r] * C_ + oc0;
                    const float* P1 = g_P + (size_t)I1s[r] * C_ + oc0;
                    float* xo = g_x + ((size_t)b * C_ + oc0) * HW_ + p0 + r;
                    #pragma unroll
                    for (int nt = 0; nt < 4; nt++) {
                        int ocl = wc * 32 + nt * 8 + (ln & 3) * 2;
                        float2 q0 = *(const float2*)(P0 + ocl);
                        float2 q1 = *(const float2*)(P1 + ocl);
                        float vx = acc[mt][nt][hf * 2 + 0] + a0 * q0.x + a1 * q1.x + bS[oc0 + ocl];
                        float vy = acc[mt][nt][hf * 2 + 1] + a0 * q0.y + a1 * q1.y + bS[oc0 + ocl + 1];
                        vx = (vx > 0.f) ? vx : 0.2f * vx;
                        vy = (vy > 0.f) ? vy : 0.2f * vy;
                        xo[(size_t)ocl * HW_] = vx;
                        xo[(size_t)(ocl + 1) * HW_] = vy;
                    }
                }
        }
        __syncthreads();   // everyone done reading B(n) / writing cand

        if (n < NCHUNK - 1) {
            #pragma unroll
            for (int i = 0; i < 16; i++) Bd[t + i * 256] = st[i];   // chunk n+1 -> smem
            if (n < NCHUNK - 2) {
                int nn = n + 2;
                const uint4* src = (nn < 8)
                    ? (const uint4*)(g_memB + nn * 65536)
                    : (const uint4*)(g_fwB + (b * 4 + (nn - 8)) * 65536);
                #pragma unroll
                for (int i = 0; i < 16; i++) st[i] = src[t + i * 256];
            }
        }
        __syncthreads();   // B(n+1) ready

        if (n == 7) {
            if (t < 128) {
                float4 ca = cand[t * 2], cb = cand[t * 2 + 1];
                float bv0 = ca.x, bv1 = ca.y;
                int   bj0 = __float_as_int(ca.z), bj1 = __float_as_int(ca.w);
                float w0 = cb.x, w1 = cb.y;
                int   j0 = __float_as_int(cb.z), j1 = __float_as_int(cb.w);
                if (w0 > bv0 || (w0 == bv0 && j0 < bj0)) {
                    float ov = bv0; int oi = bj0;
                    bv0 = w0; bj0 = j0;
                    if (ov > w1 || (ov == w1 && oi < j1)) { bv1 = ov; bj1 = oi; }
                    else { bv1 = w1; bj1 = j1; }
                } else if (w0 > bv1 || (w0 == bv1 && j0 < bj1)) {
                    bv1 = w0; bj1 = j0;
                }
                float e = expf(bv1 - bv0);
                float a0 = 1.f / (1.f + e);
                A0s[t] = a0; A1s[t] = e * a0; I0s[t] = bj0; I1s[t] = bj1;
            }
            __syncthreads();
        }
    }
}

// ---------------- K4: depthwise dilated 3x3 (d=2) + bias + leaky ----------------
__global__ void k_dw(const float* __restrict__ dw, const float* __restrict__ db,
                     float* __restrict__ out) {
    __shared__ float sx[4096];
    __shared__ float w[9];
    int bc = blockIdx.x;
    int c = bc & 255;
    int t = threadIdx.x;
    const float* xin = g_x + (size_t)bc * HW_;
    for (int i = t; i < 4096; i += 256) sx[i] = xin[i];
    if (t < 9) w[t] = dw[c * 9 + t];
    __syncthreads();
    float bias = db[c];
    for (int p = t; p < 4096; p += 256) {
        int y = p >> 6, x = p & 63;
        float s = bias;
        #pragma unroll
        for (int ky = 0; ky < 3; ky++) {
            int iy = y + 2 * ky - 2;
            if ((unsigned)iy < 64u) {
                #pragma unroll
                for (int kx = 0; kx < 3; kx++) {
                    int ix = x + 2 * kx - 2;
                    if ((unsigned)ix < 64u) s += w[ky * 3 + kx] * sx[(iy << 6) + ix];
                }
            }
        }
        out[(size_t)bc * HW_ + p] = (s > 0.f) ? s : 0.2f * s;
    }
}

extern "C" void kernel_launch(void* const* d_in, const int* in_sizes, int n_in,
                              void* d_out, int out_size) {
    const float* img = (const float*)d_in[0];
    const float* mem = (const float*)d_in[1];
    const float* fw  = (const float*)d_in[2];
    const float* fb  = (const float*)d_in[3];
    const float* dw  = (const float*)d_in[4];
    const float* db  = (const float*)d_in[5];
    float* out = (float*)d_out;

    cudaFuncSetAttribute(k_main, cudaFuncAttributeMaxDynamicSharedMemorySize, SMEM_MAIN);

    k_mean<<<B_ * C_, 256>>>(img);
    k_global<<<B_, 256>>>(mem);
    k_pmat<<<M_, 256>>>(mem, fw);
    k_prep<<<32, 256>>>(mem);
    k_prepw<<<128, 256>>>(fw);
    k_main<<<B_ * (HW_ / 128), 256, SMEM_MAIN>>>(img, fb);
    k_dw<<<B_ * C_, 256>>>(dw, db, out);
}

// round 8
// speedup vs baseline: 2.8634x; 1.1532x over previous
#include <cuda_runtime.h>
#include <cuda_bf16.h>
#include <cstdint>

#define B_  8
#define C_  256
#define HW_ 4096
#define M_  512

// ---------------- device scratch ----------------
__device__ float g_IG[B_ * C_];
__device__ float g_gate[B_ * C_];
__device__ float g_P[M_ * C_];                    // P[m][o] = sum_c W2[o][c]*mem[m][c]
__device__ float g_x[(size_t)B_ * C_ * HW_];      // pre-depthwise activations
__device__ unsigned char g_memB[8 * 65536];       // pre-built B fragment images: memory (8 chunks)
__device__ unsigned char g_fwB[B_ * 4 * 65536];   // pre-built B fragment images: gated fusion_w (per batch)

// ---------------- helpers ----------------
static __device__ __forceinline__ void mma_bf16(float* c,
    uint32_t a0, uint32_t a1, uint32_t a2, uint32_t a3, uint32_t b0, uint32_t b1) {
    asm("mma.sync.aligned.m16n8k16.row.col.f32.bf16.bf16.f32 "
        "{%0,%1,%2,%3}, {%4,%5,%6,%7}, {%8,%9}, {%0,%1,%2,%3};"
        : "+f"(c[0]), "+f"(c[1]), "+f"(c[2]), "+f"(c[3])
        : "r"(a0), "r"(a1), "r"(a2), "r"(a3), "r"(b0), "r"(b1));
}
static __device__ __forceinline__ void split_bf16(float v, unsigned short& hb, unsigned short& lb) {
    __nv_bfloat16 h = __float2bfloat16_rn(v);
    __nv_bfloat16 l = __float2bfloat16_rn(v - __bfloat162float(h));
    hb = *(unsigned short*)&h;
    lb = *(unsigned short*)&l;
}
static __device__ __forceinline__ uint32_t pk(unsigned short a, unsigned short b) {
    return (uint32_t)a | ((uint32_t)b << 16);
}

// ---------------- K1: per-(b,c) spatial mean ----------------
__global__ void k_mean(const float* __restrict__ img) {
    __shared__ float red[256];
    int bc = blockIdx.x;
    const float4* p = (const float4*)(img + (size_t)bc * HW_);
    float s = 0.f;
    for (int i = threadIdx.x; i < HW_ / 4; i += 256) {
        float4 v = p[i];
        s += (v.x + v.y) + (v.z + v.w);
    }
    red[threadIdx.x] = s;
    __syncthreads();
    for (int st = 128; st > 0; st >>= 1) {
        if (threadIdx.x < st) red[threadIdx.x] += red[threadIdx.x + st];
        __syncthreads();
    }
    if (threadIdx.x == 0) g_IG[bc] = red[0] * (1.f / (float)HW_);
}

// ---------------- K2: global path -> gate ----------------
__global__ void k_global(const float* __restrict__ mem) {
    __shared__ float sc[M_];
    __shared__ float ig[C_];
    __shared__ float red[256];
    int b = blockIdx.x, t = threadIdx.x;
    ig[t] = g_IG[b * C_ + t];
    __syncthreads();
    #pragma unroll
    for (int r = 0; r < 2; r++) {
        int m = t + r * 256;
        const float* mr = mem + (size_t)m * C_;
        float a = 0.f;
        for (int c = 0; c < C_; c += 4) {
            float4 mv = *(const float4*)(mr + c);
            a += ig[c] * mv.x + ig[c + 1] * mv.y + ig[c + 2] * mv.z + ig[c + 3] * mv.w;
        }
        sc[m] = a;
    }
    __syncthreads();
    red[t] = fmaxf(sc[t], sc[t + 256]);
    __syncthreads();
    for (int st = 128; st > 0; st >>= 1) {
        if (t < st) red[t] = fmaxf(red[t], red[t + st]);
        __syncthreads();
    }
    float mx = red[0];
    __syncthreads();
    float e0 = expf(sc[t] - mx), e1 = expf(sc[t + 256] - mx);
    sc[t] = e0; sc[t + 256] = e1;
    red[t] = e0 + e1;
    __syncthreads();
    for (int st = 128; st > 0; st >>= 1) {
        if (t < st) red[t] += red[t + st];
        __syncthreads();
    }
    float inv = 1.f / red[0];
    float acc = 0.f;
    for (int m = 0; m < M_; m++) acc += sc[m] * mem[(size_t)m * C_ + t];
    float mr2 = acc * inv + ig[t];
    g_gate[b * C_ + t] = 1.f / (1.f + expf(-mr2));
}

// ---------------- K2p: P[m][o] = W2[o,:] . mem[m,:] ----------------
__global__ void k_pmat(const float* __restrict__ mem, const float* __restrict__ fw) {
    __shared__ float row[C_];
    int m = blockIdx.x, o = threadIdx.x;
    row[o] = mem[(size_t)m * C_ + o];
    __syncthreads();
    const float* wr = fw + (size_t)o * 512 + 256;
    float a = 0.f;
    for (int c = 0; c < C_; c += 4) {
        float4 w4 = *(const float4*)(wr + c);
        a += w4.x * row[c] + w4.y * row[c + 1] + w4.z * row[c + 2] + w4.w * row[c + 3];
    }
    g_P[m * C_ + o] = a;
}

// ---------------- K2m: memory -> B fragment images (whole-slot writes) ----------------
__global__ void k_prep(const float* __restrict__ mem) {
    int u = blockIdx.x * 256 + threadIdx.x;   // 8192 = 512 m x 16 ks
    int ks = u >> 9;
    int m  = u & 511;
    const float* mr = mem + (size_t)m * C_ + ks * 16;
    unsigned short hs[16], ls[16];
    #pragma unroll
    for (int kin = 0; kin < 16; kin++) split_bf16(mr[kin], hs[kin], ls[kin]);
    int ch = m >> 6, rr = m & 63, nt = rr >> 3, nn = rr & 7;
    uint4* dst = (uint4*)(g_memB + ch * 65536) + (nt * 16 + ks) * 32 + nn * 4;
    #pragma unroll
    for (int j = 0; j < 4; j++)
        dst[j] = make_uint4(pk(hs[2*j], hs[2*j+1]), pk(hs[8+2*j], hs[8+2*j+1]),
                            pk(ls[2*j], ls[2*j+1]), pk(ls[8+2*j], ls[8+2*j+1]));
}

// ---------------- K2w: gated fusion_w -> B fragment images per batch ----------------
__global__ void k_prepw(const float* __restrict__ fw) {
    int u = blockIdx.x * 256 + threadIdx.x;   // 32768 = 16 ks x 8 b x 256 r
    int ks = u >> 11;
    int b  = (u >> 8) & 7;
    int r  = u & 255;
    const float* wr = fw + (size_t)r * 512 + ks * 16;
    const float* gt = g_gate + b * C_ + ks * 16;
    unsigned short hs[16], ls[16];
    #pragma unroll
    for (int kin = 0; kin < 16; kin++) split_bf16(wr[kin] * gt[kin], hs[kin], ls[kin]);
    int ch = r >> 6, rr = r & 63, nt = rr >> 3, nn = rr & 7;
    uint4* dst = (uint4*)(g_fwB + (b * 4 + ch) * 65536) + (nt * 16 + ks) * 32 + nn * 4;
    #pragma unroll
    for (int j = 0; j < 4; j++)
        dst[j] = make_uint4(pk(hs[2*j], hs[2*j+1]), pk(hs[8+2*j], hs[8+2*j+1]),
                            pk(ls[2*j], ls[2*j+1]), pk(ls[8+2*j], ls[8+2*j+1]));
}

// ---------------- K3: main fused kernel (512 threads) ----------------
// A half (padded) = 4096*16 + 512*16 = 73728 B
// smem: A_h [0,73728), A_l [73728,147456), B [147456,212992), small [212992,220160)
#define OFF_AL 73728
#define OFF_B  147456
#define OFF_SM 212992
#define SMEM_MAIN 220160
#define NCHUNK 12

#define UPD(slot, val, idx) do { float _v = (val); \
    if (_v > v0[slot]) { v1[slot] = v0[slot]; i1[slot] = i0[slot]; v0[slot] = _v; i0[slot] = (idx); } \
    else if (_v > v1[slot]) { v1[slot] = _v; i1[slot] = (idx); } } while (0)

// padded A slot byte offset: 16B slot + 16B pad per 8 slots (keeps 16B alignment)
static __device__ __forceinline__ uint32_t apad(int s) {
    return ((uint32_t)s << 4) + (((uint32_t)s >> 3) << 4);
}

// warp tile 16 px x 32 n; 3-pass split-bf16 (hh + hl + lh)
static __device__ __forceinline__ void chunk_mma(const unsigned char* sm,
                                                 int wr, int wc, int ln, float acc[4][4]) {
    const uint4* Bfr = (const uint4*)(sm + OFF_B);
    const int sA = wr * 512 + ln;
    #pragma unroll
    for (int ks = 0; ks < 16; ks++) {
        int s = sA + ks * 32;
        uint4 ah = *(const uint4*)(sm + apad(s));
        uint4 al = *(const uint4*)(sm + OFF_AL + apad(s));
        #pragma unroll
        for (int nt = 0; nt < 4; nt++) {
            uint4 bv = Bfr[((wc * 4 + nt) * 16 + ks) * 32 + ln];
            mma_bf16(acc[nt], ah.x, ah.y, ah.z, ah.w, bv.x, bv.y);  // hh
            mma_bf16(acc[nt], ah.x, ah.y, ah.z, ah.w, bv.z, bv.w);  // h*l
            mma_bf16(acc[nt], al.x, al.y, al.z, al.w, bv.x, bv.y);  // l*h
        }
    }
}

__global__ void __launch_bounds__(512, 1) k_main(
    const float* __restrict__ img, const float* __restrict__ fb)
{
    extern __shared__ unsigned char sm[];
    const int t  = threadIdx.x;
    const int b  = blockIdx.x >> 5;
    const int p0 = (blockIdx.x & 31) * 128;
    const int w  = t >> 5;          // warp 0..15
    const int ln = t & 31;
    const int wr = w >> 1;          // px tile 0..7 (16 px each)
    const int wc = w & 1;           // n half 0..1 (32 n each)

    float*  A0s  = (float*)(sm + OFF_SM);
    float*  A1s  = (float*)(sm + OFF_SM + 512);
    int*    I0s  = (int*)  (sm + OFF_SM + 1024);
    int*    I1s  = (int*)  (sm + OFF_SM + 1536);
    float*  bS   = (float*)(sm + OFF_SM + 2048);
    float4* cand = (float4*)(sm + OFF_SM + 3072);

    uint4 st[8];
    uint4* Bd = (uint4*)(sm + OFF_B);

    // LDG chunk 0
    {
        const uint4* src = (const uint4*)g_memB;
        #pragma unroll
        for (int i = 0; i < 8; i++) st[i] = src[t + i * 512];
    }

    // ---- stage A: unit = (row-pair rp, ks); whole 16B slots, padded layout ----
    {
        const float* ib = img + (size_t)b * C_ * HW_ + p0;
        #pragma unroll
        for (int u0 = 0; u0 < 2; u0++) {
            int u = t + u0 * 512;
            int rp = u & 63, ks = u >> 6;
            int pxl = (rp >> 3) * 16 + (rp & 7);
            const float* ibc = ib + (size_t)(ks * 16) * HW_;
            unsigned short hlo[16], llo[16], hhi[16], lhi[16];
            #pragma unroll
            for (int kin = 0; kin < 16; kin++) {
                split_bf16(ibc[(size_t)kin * HW_ + pxl],     hlo[kin], llo[kin]);
                split_bf16(ibc[(size_t)kin * HW_ + pxl + 8], hhi[kin], lhi[kin]);
            }
            int s0 = ((rp >> 3) * 16 + ks) * 32 + (rp & 7) * 4;
            #pragma unroll
            for (int j = 0; j < 4; j++) {
                uint32_t ap = apad(s0 + j);
                *(uint4*)(sm + ap) =
                    make_uint4(pk(hlo[2*j], hlo[2*j+1]), pk(hhi[2*j], hhi[2*j+1]),
                               pk(hlo[8+2*j], hlo[8+2*j+1]), pk(hhi[8+2*j], hhi[8+2*j+1]));
                *(uint4*)(sm + OFF_AL + ap) =
                    make_uint4(pk(llo[2*j], llo[2*j+1]), pk(lhi[2*j], lhi[2*j+1]),
                               pk(llo[8+2*j], llo[8+2*j+1]), pk(lhi[8+2*j], lhi[8+2*j+1]));
            }
        }
    }
    if (t < 256) bS[t] = fb[t];

    // STS chunk 0, LDG chunk 1
    #pragma unroll
    for (int i = 0; i < 8; i++) Bd[t + i * 512] = st[i];
    {
        const uint4* src = (const uint4*)(g_memB + 65536);
        #pragma unroll
        for (int i = 0; i < 8; i++) st[i] = src[t + i * 512];
    }
    __syncthreads();

    float v0[2], v1[2];
    int   i0[2], i1[2];
    #pragma unroll
    for (int s = 0; s < 2; s++) { v0[s] = -3.402823466e38f; v1[s] = -3.402823466e38f; i0[s] = 0; i1[s] = 0; }

    for (int n = 0; n < NCHUNK; n++) {
        float acc[4][4];
        #pragma unroll
        for (int nt = 0; nt < 4; nt++)
            #pragma unroll
            for (int q = 0; q < 4; q++) acc[nt][q] = 0.f;

        chunk_mma(sm, wr, wc, ln, acc);

        if (n < 8) {
            // ---- scores: running top-2 (registers) ----
            #pragma unroll
            for (int nt = 0; nt < 4; nt++) {
                int mi = n * 64 + (wc * 4 + nt) * 8 + (ln & 3) * 2;
                UPD(0, acc[nt][0], mi);
                UPD(0, acc[nt][1], mi + 1);
                UPD(1, acc[nt][2], mi);
                UPD(1, acc[nt][3], mi + 1);
            }
            if (n == 7) {
                // shfl-merge across the 4 lanes sharing each pixel, publish per-wc candidate
                #pragma unroll
                for (int s = 0; s < 2; s++) {
                    #pragma unroll
                    for (int d = 1; d <= 2; d <<= 1) {
                        float w0 = __shfl_xor_sync(0xFFFFFFFFu, v0[s], d);
                        float w1 = __shfl_xor_sync(0xFFFFFFFFu, v1[s], d);
                        int   j0 = __shfl_xor_sync(0xFFFFFFFFu, i0[s], d);
                        int   j1 = __shfl_xor_sync(0xFFFFFFFFu, i1[s], d);
                        if (w0 > v0[s] || (w0 == v0[s] && j0 < i0[s])) {
                            float ov = v0[s]; int oi = i0[s];
                            v0[s] = w0; i0[s] = j0;
                            if (ov > w1 || (ov == w1 && oi < j1)) { v1[s] = ov; i1[s] = oi; }
                            else { v1[s] = w1; i1[s] = j1; }
                        } else if (w0 > v1[s] || (w0 == v1[s] && j0 < i1[s])) {
                            v1[s] = w0; i1[s] = j0;
                        }
                    }
                    if ((ln & 3) == 0) {
                        int r = wr * 16 + s * 8 + (ln >> 2);
                        cand[r * 2 + wc] = make_float4(v0[s], v1[s],
                                                       __int_as_float(i0[s]), __int_as_float(i1[s]));
                    }
                }
            }
        } else {
            // ---- fusion epilogue: + a0*P[i0] + a1*P[i1] + bias, leaky, direct store ----
            int oc0 = (n - 8) * 64;
            #pragma unroll
            for (int hf = 0; hf < 2; hf++) {
                int r = wr * 16 + hf * 8 + (ln >> 2);
                float a0 = A0s[r], a1 = A1s[r];
                const float* P0 = g_P + (size_t)I0s[r] * C_ + oc0;
                const float* P1 = g_P + (size_t)I1s[r] * C_ + oc0;
                float* xo = g_x + ((size_t)b * C_ + oc0) * HW_ + p0 + r;
                #pragma unroll
                for (int nt = 0; nt < 4; nt++) {
                    int ocl = wc * 32 + nt * 8 + (ln & 3) * 2;
                    float2 q0 = *(const float2*)(P0 + ocl);
                    float2 q1 = *(const float2*)(P1 + ocl);
                    float vx = acc[nt][hf * 2 + 0] + a0 * q0.x + a1 * q1.x + bS[oc0 + ocl];
                    float vy = acc[nt][hf * 2 + 1] + a0 * q0.y + a1 * q1.y + bS[oc0 + ocl + 1];
                    vx = (vx > 0.f) ? vx : 0.2f * vx;
                    vy = (vy > 0.f) ? vy : 0.2f * vy;
                    xo[(size_t)ocl * HW_] = vx;
                    xo[(size_t)(ocl + 1) * HW_] = vy;
                }
            }
        }
        __syncthreads();   // everyone done reading B(n) / writing cand

        if (n < NCHUNK - 1) {
            #pragma unroll
            for (int i = 0; i < 8; i++) Bd[t + i * 512] = st[i];   // chunk n+1 -> smem
            if (n < NCHUNK - 2) {
                int nn = n + 2;
                const uint4* src = (nn < 8)
                    ? (const uint4*)(g_memB + nn * 65536)
                    : (const uint4*)(g_fwB + (b * 4 + (nn - 8)) * 65536);
                #pragma unroll
                for (int i = 0; i < 8; i++) st[i] = src[t + i * 512];
            }
        }
        __syncthreads();   // B(n+1) ready

        if (n == 7) {
            if (t < 128) {
                float4 ca = cand[t * 2], cb = cand[t * 2 + 1];
                float bv0 = ca.x, bv1 = ca.y;
                int   bj0 = __float_as_int(ca.z), bj1 = __float_as_int(ca.w);
                float w0 = cb.x, w1 = cb.y;
                int   j0 = __float_as_int(cb.z), j1 = __float_as_int(cb.w);
                if (w0 > bv0 || (w0 == bv0 && j0 < bj0)) {
                    float ov = bv0; int oi = bj0;
                    bv0 = w0; bj0 = j0;
                    if (ov > w1 || (ov == w1 && oi < j1)) { bv1 = ov; bj1 = oi; }
                    else { bv1 = w1; bj1 = j1; }
                } else if (w0 > bv1 || (w0 == bv1 && j0 < bj1)) {
                    bv1 = w0; bj1 = j0;
                }
                float e = expf(bv1 - bv0);
                float a0 = 1.f / (1.f + e);
                A0s[t] = a0; A1s[t] = e * a0; I0s[t] = bj0; I1s[t] = bj1;
            }
            __syncthreads();
        }
    }
}

// ---------------- K4: depthwise dilated 3x3 (d=2) + bias + leaky ----------------
__global__ void k_dw(const float* __restrict__ dw, const float* __restrict__ db,
                     float* __restrict__ out) {
    __shared__ float sx[4096];
    __shared__ float w[9];
    int bc = blockIdx.x;
    int c = bc & 255;
    int t = threadIdx.x;
    const float* xin = g_x + (size_t)bc * HW_;
    for (int i = t; i < 4096; i += 256) sx[i] = xin[i];
    if (t < 9) w[t] = dw[c * 9 + t];
    __syncthreads();
    float bias = db[c];
    for (int p = t; p < 4096; p += 256) {
        int y = p >> 6, x = p & 63;
        float s = bias;
        #pragma unroll
        for (int ky = 0; ky < 3; ky++) {
            int iy = y + 2 * ky - 2;
            if ((unsigned)iy < 64u) {
                #pragma unroll
                for (int kx = 0; kx < 3; kx++) {
                    int ix = x + 2 * kx - 2;
                    if ((unsigned)ix < 64u) s += w[ky * 3 + kx] * sx[(iy << 6) + ix];
                }
            }
        }
        out[(size_t)bc * HW_ + p] = (s > 0.f) ? s : 0.2f * s;
    }
}

extern "C" void kernel_launch(void* const* d_in, const int* in_sizes, int n_in,
                              void* d_out, int out_size) {
    const float* img = (const float*)d_in[0];
    const float* mem = (const float*)d_in[1];
    const float* fw  = (const float*)d_in[2];
    const float* fb  = (const float*)d_in[3];
    const float* dw  = (const float*)d_in[4];
    const float* db  = (const float*)d_in[5];
    float* out = (float*)d_out;

    cudaFuncSetAttribute(k_main, cudaFuncAttributeMaxDynamicSharedMemorySize, SMEM_MAIN);

    k_mean<<<B_ * C_, 256>>>(img);
    k_global<<<B_, 256>>>(mem);
    k_pmat<<<M_, 256>>>(mem, fw);
    k_prep<<<32, 256>>>(mem);
    k_prepw<<<128, 256>>>(fw);
    k_main<<<B_ * (HW_ / 128), 512, SMEM_MAIN>>>(img, fb);
    k_dw<<<B_ * C_, 256>>>(dw, db, out);
}